// round 10
// baseline (speedup 1.0000x reference)
#include <cuda_runtime.h>
#include <cstdint>
#include <cstddef>

// Problem constants (fixed by the reference)
#define BB 256
#define CC 32
#define HH 64
#define WW 64
#define PW 68           // padded width/height (2-px zero ring for 5x5 SAME)
#define PIMG (PW*PW)    // 4624

#define CHUNK 8                  // input channels per tile pass (= #warps)
#define TROWS 10                 // padded rows per tile (6 out + 4 halo)
#define CROWS (TROWS*PW)         // 680 floats per channel slab
#define TSZ   (CHUNK*CROWS)      // 5440 floats per tile
#define NYT   11                 // ceil(64/6) output row tiles

#define CHUNK3 16                // conv3k channel chunk

// ---------------------------------------------------------------------------
// Device-global scratch (allocation-free rule: __device__ globals only).
// ---------------------------------------------------------------------------
__device__ float g_h [(size_t)BB * CC * PIMG];   // rotated input, padded
__device__ float g_y1[(size_t)BB * 64 * PIMG];   // conv1 output, padded
__device__ float g_y2[(size_t)BB * 64 * PIMG];   // conv2 output, padded

// ---------------------------------------------------------------------------
// Packed dual-fp32 helpers (full-rate fp32 path on Blackwell)
// ---------------------------------------------------------------------------
__device__ __forceinline__ void fma2(unsigned long long& d,
                                     unsigned long long a,
                                     unsigned long long b) {
    asm("fma.rn.f32x2 %0, %1, %2, %0;" : "+l"(d) : "l"(a), "l"(b));
}

// (hi32(a), lo32(b)) -> one f32x2 pair; pure register MOVs (ALU pipe).
__device__ __forceinline__ unsigned long long pack_hl(unsigned long long a,
                                                      unsigned long long b) {
    unsigned long long r;
    asm("{\n\t"
        ".reg .b32 al, ah, bl, bh;\n\t"
        "mov.b64 {al, ah}, %1;\n\t"
        "mov.b64 {bl, bh}, %2;\n\t"
        "mov.b64 %0, {ah, bl};\n\t"
        "}"
        : "=l"(r) : "l"(a), "l"(b));
    return r;
}

// 16B broadcast load of two adjacent u64 weight duplicates.
__device__ __forceinline__ void lds_v2u64(unsigned long long& a,
                                          unsigned long long& b,
                                          const void* p) {
    unsigned int addr = (unsigned int)__cvta_generic_to_shared(p);
    asm("ld.shared.v2.u64 {%0, %1}, [%2];" : "=l"(a), "=l"(b) : "r"(addr));
}

// ---------------------------------------------------------------------------
// Kernel 1: rotation (separable because source rows are replicated).
// ---------------------------------------------------------------------------
__global__ void rotate_kernel(const float* __restrict__ xin,
                              float* __restrict__ hout)
{
    const int bc = blockIdx.x;          // b*32 + c
    const int c  = bc & (CC - 1);

    __shared__ float row[WW];
    if (threadIdx.x < WW) row[threadIdx.x] = xin[(size_t)bc * WW + threadIdx.x];
    __syncthreads();

    const float ang = (-180.0f / 32.0f) * (float)c * 0.017453292519943295f;
    float si, co;
    sincosf(ang, &si, &co);

    float* dst = hout + (size_t)bc * PIMG;
    for (int p = threadIdx.x; p < PIMG; p += blockDim.x) {
        const int py = p / PW;
        const int px = p - py * PW;
        const int y = py - 2, x = px - 2;
        float val = 0.f;
        if ((unsigned)y < 64u && (unsigned)x < 64u) {
            const float xx = (float)x - 31.5f;
            const float yy = (float)y - 31.5f;
            const float xs = co * xx + si * yy + 31.5f;
            const float ys = co * yy - si * xx + 31.5f;
            const float x0f = floorf(xs);
            const float y0f = floorf(ys);
            const int x0  = (int)x0f;
            const int y0i = (int)y0f;
            const float wx1 = xs - x0f, wx0 = 1.f - wx1;
            const float wy1 = ys - y0f, wy0 = 1.f - wy1;
            float fy = 0.f;
            if ((unsigned)y0i       < 64u) fy += wy0;
            if ((unsigned)(y0i + 1) < 64u) fy += wy1;
            float fx = 0.f;
            if ((unsigned)x0       < 64u) fx += wx0 * row[x0];
            if ((unsigned)(x0 + 1) < 64u) fx += wx1 * row[x0 + 1];
            val = fy * fx;
        }
        dst[p] = val;
    }
}

// ---------------------------------------------------------------------------
// Re-zero the padding rings of the conv scratch buffers each launch.
// ---------------------------------------------------------------------------
__global__ void zero_borders(float* __restrict__ a, float* __restrict__ b)
{
    const int bc = blockIdx.x;          // b*64 + ch
    float* pa = a + (size_t)bc * PIMG;
    float* pb = b + (size_t)bc * PIMG;
    for (int p = threadIdx.x; p < 528; p += blockDim.x) {
        int off;
        if (p < 136)        off = p;                         // rows 0,1
        else if (p < 272)   off = 66 * PW + (p - 136);       // rows 66,67
        else {
            const int q = p - 272;
            const int r = 2 + (q >> 2);                      // rows 2..65
            const int cc4 = q & 3;
            const int col = (cc4 < 2) ? cc4 : 64 + cc4;      // cols 0,1,66,67
            off = r * PW + col;
        }
        pa[off] = 0.f;
        pb[off] = 0.f;
    }
}

// ---------------------------------------------------------------------------
// 5x5 SAME conv, CIN -> 64, ReLU.
// Grid = b*(NYT*4) + ytile*4 + ocq. Block 256 thr = 8 warps.
//   warp w -> 2 output channels: ocq*16 + w*2 .. +2
//   lane l -> cols {2l,2l+1} as f32x2; 6 output rows per thread
// Crossbar-minimal inner loop: each tile row loaded ONCE per channel as
// 3x LDS.64 (cols 0..5); odd-kx pairs synthesized via register packs (ALU);
// weights fetched as one 16B broadcast per (ky,kx) feeding both oc's.
// ---------------------------------------------------------------------------
template <int CIN>
__global__ void __launch_bounds__(256, 2)
conv5x5_relu(const float* __restrict__ in,    // [B][CIN][68][68]
             const float* __restrict__ w,     // [64][CIN][5][5]
             const float* __restrict__ bias,  // [64]
             float* __restrict__ out)         // [B][64][68][68]
{
    extern __shared__ float smem[];
    float*  tileA = smem;                      // TSZ floats
    float2* wsm   = (float2*)(smem + TSZ);     // 8 warps x 2 bufs x 50 f2

    const int blk   = blockIdx.x;
    const int ocq   = blk & 3;
    const int rest  = blk >> 2;
    const int ytile = rest % NYT;
    const int b     = rest / NYT;
    const int y0    = ytile * 6;               // first output row of tile

    const int warp   = threadIdx.x >> 5;
    const int lane   = threadIdx.x & 31;
    const int ocbase = ocq * 16 + warp * 2;

    // ---- hoisted weight-staging indexing ----
    // warp's 50 floats, interleaved [k][j]: slot idx = lane + it*32 (<50)
    int  goff[2];
    bool act[2];
#pragma unroll
    for (int it = 0; it < 2; ++it) {
        const int idx = lane + it * 32;
        act[it] = (idx < 50);
        const int j = idx & 1;
        const int k = idx >> 1;
        goff[it] = act[it] ? (((ocbase + j) * CIN) * 25 + k) : 0;
    }
    float wreg[2];
#pragma unroll
    for (int it = 0; it < 2; ++it)
        wreg[it] = act[it] ? w[goff[it]] : 0.f;

    unsigned long long acc[2][6];
#pragma unroll
    for (int j = 0; j < 2; ++j)
#pragma unroll
        for (int yr = 0; yr < 6; ++yr) acc[j][yr] = 0ull;

    // ragged last ytile: clamp loads at image bottom (rows >= 68 read as 0)
    const int maxpos = min(CROWS, (68 - y0) * PW);

    constexpr int NCHUNK = CIN / CHUNK;
#pragma unroll 1
    for (int chunk = 0; chunk < NCHUNK; ++chunk) {
        __syncthreads();   // previous chunk fully consumed
        const float* srcc = in + ((size_t)b * CIN + chunk * CHUNK + warp) * PIMG
                               + (size_t)y0 * PW;
        const int ibase = warp * CROWS;
#pragma unroll
        for (int jj = 0; jj < 22; ++jj) {       // 22*32 >= 680
            const int pos = lane + jj * 32;
            if (pos < CROWS)
                tileA[ibase + pos] = (pos < maxpos) ? srcc[pos] : 0.f;
        }
        __syncthreads();

#pragma unroll 1
        for (int cl = 0; cl < CHUNK; ++cl) {
            const int c = chunk * CHUNK + cl;

            // ---- stage prefetched weights (channel c), dup'd [k][j] ----
            float2* wb = wsm + (size_t)(warp * 2 + (c & 1)) * 50;
#pragma unroll
            for (int it = 0; it < 2; ++it) {
                const int idx = lane + it * 32;
                if (act[it]) wb[idx] = make_float2(wreg[it], wreg[it]);
            }
            __syncwarp();

            // ---- prefetch channel c+1 weights (pointer bump only) ----
            if (c + 1 < CIN) {
#pragma unroll
                for (int it = 0; it < 2; ++it)
                    if (act[it]) wreg[it] = w[goff[it] + (c + 1) * 25];
            }

            // ---- load each tile row once: cols 0..5 as 3x LDS.64 ----
            const float* ta = tileA + cl * CROWS + 2 * lane;
            unsigned long long RA[TROWS], RB[TROWS], RC[TROWS];
#pragma unroll
            for (int r = 0; r < TROWS; ++r) {
                RA[r] = *(const unsigned long long*)(ta + r * PW);
                RB[r] = *(const unsigned long long*)(ta + r * PW + 2);
                RC[r] = *(const unsigned long long*)(ta + r * PW + 4);
            }

            const unsigned long long* wu = (const unsigned long long*)wb;
#pragma unroll
            for (int ky = 0; ky < 5; ++ky) {
#pragma unroll
                for (int kx = 0; kx < 5; ++kx) {
                    unsigned long long w0, w1;
                    lds_v2u64(w0, w1, wu + (ky * 5 + kx) * 2);
#pragma unroll
                    for (int yr = 0; yr < 6; ++yr) {
                        const int r = ky + yr;
                        unsigned long long p;
                        if      (kx == 0) p = RA[r];
                        else if (kx == 1) p = pack_hl(RA[r], RB[r]);
                        else if (kx == 2) p = RB[r];
                        else if (kx == 3) p = pack_hl(RB[r], RC[r]);
                        else              p = RC[r];
                        fma2(acc[0][yr], w0, p);
                        fma2(acc[1][yr], w1, p);
                    }
                }
            }
        }
    }

    // ---- epilogue: bias + ReLU, write padded interior ----
    const size_t ob = (size_t)b * 64;
#pragma unroll
    for (int j = 0; j < 2; ++j) {
        const int oc = ocbase + j;
        const float bv = bias[oc];
#pragma unroll
        for (int yr = 0; yr < 6; ++yr) {
            if (y0 + yr < 64) {
                const float lo = __uint_as_float((unsigned)(acc[j][yr] & 0xffffffffull));
                const float hi = __uint_as_float((unsigned)(acc[j][yr] >> 32));
                float2 o;
                o.x = fmaxf(lo + bv, 0.f);
                o.y = fmaxf(hi + bv, 0.f);
                *(float2*)(out + (ob + oc) * PIMG
                               + (size_t)(y0 + 2 + yr) * PW + 2 + 2 * lane) = o;
            }
        }
    }
}

// ---------------------------------------------------------------------------
// Final 5x5 conv, 64 -> 1, writes d_out (B,64,64). Channel-chunked smem,
// 4 blocks/SM.
// ---------------------------------------------------------------------------
__global__ void __launch_bounds__(256, 4)
conv3k(const float* __restrict__ in,   // [B][64][68][68]
       const float* __restrict__ w2,   // [1][64][5][5]
       const float* __restrict__ b2,   // [1]
       float* __restrict__ out)        // [B][64][64]
{
    extern __shared__ float smem[];
    float* tile = smem;                     // CHUNK3*8*68
    float* ws   = smem + CHUNK3 * 8 * PW;   // 1600

    const int blk   = blockIdx.x;
    const int ytile = blk & 15;
    const int b     = blk >> 4;
    const int y0    = ytile * 4;

    for (int i = threadIdx.x; i < 1600; i += 256) ws[i] = w2[i];

    const int yr = threadIdx.x >> 6;    // 0..3
    const int x  = threadIdx.x & 63;    // 0..63
    float acc = b2[0];

#pragma unroll 1
    for (int chunk = 0; chunk < 64 / CHUNK3; ++chunk) {
        __syncthreads();
        const float* src = in + ((size_t)b * 64 + chunk * CHUNK3) * PIMG
                              + (size_t)y0 * PW;
        for (int i = threadIdx.x; i < CHUNK3 * 8 * PW; i += 256) {
            const int ch = i / (8 * PW);
            const int r  = i - ch * (8 * PW);
            tile[i] = src[(size_t)ch * PIMG + r];
        }
        __syncthreads();

#pragma unroll 1
        for (int cl = 0; cl < CHUNK3; ++cl) {
            const float* t  = tile + cl * (8 * PW) + yr * PW + x;
            const float* wc = ws + (chunk * CHUNK3 + cl) * 25;
#pragma unroll
            for (int ky = 0; ky < 5; ++ky)
#pragma unroll
                for (int kx = 0; kx < 5; ++kx)
                    acc += wc[ky * 5 + kx] * t[ky * PW + kx];
        }
    }
    out[(size_t)b * 4096 + (size_t)(y0 + yr) * 64 + x] = acc;
}

// ---------------------------------------------------------------------------
// kernel_launch (graph-capturable: kernel launches + non-stream queries only)
// Input order per metadata: x, w0, b0, w1, b1, w2, b2 (all fp32).
// ---------------------------------------------------------------------------
extern "C" void kernel_launch(void* const* d_in, const int* in_sizes, int n_in,
                              void* d_out, int out_size)
{
    (void)in_sizes; (void)n_in; (void)out_size;

    const float* x  = (const float*)d_in[0];
    const float* w0 = (const float*)d_in[1];
    const float* b0 = (const float*)d_in[2];
    const float* w1 = (const float*)d_in[3];
    const float* b1 = (const float*)d_in[4];
    const float* w2 = (const float*)d_in[5];
    const float* b2 = (const float*)d_in[6];
    float* out = (float*)d_out;

    void *ph, *py1, *py2;
    cudaGetSymbolAddress(&ph,  g_h);
    cudaGetSymbolAddress(&py1, g_y1);
    cudaGetSymbolAddress(&py2, g_y2);

    // tileA + per-warp weight double buffers (50 f2 x 2 x 8 warps)
    constexpr int SMEMC = TSZ * 4 + 8 * 2 * 50 * 8;          // 28,160 B
    constexpr int SMEM3 = (CHUNK3 * 8 * PW + 1600) * 4;      // 41,216 B

    cudaFuncSetAttribute(conv5x5_relu<32>,
                         cudaFuncAttributeMaxDynamicSharedMemorySize, SMEMC);
    cudaFuncSetAttribute(conv5x5_relu<64>,
                         cudaFuncAttributeMaxDynamicSharedMemorySize, SMEMC);
    cudaFuncSetAttribute(conv3k,
                         cudaFuncAttributeMaxDynamicSharedMemorySize, SMEM3);

    rotate_kernel<<<BB * CC, 128>>>(x, (float*)ph);
    zero_borders<<<BB * 64, 128>>>((float*)py1, (float*)py2);
    // grid: (b*NYT + ytile)*4 + ocq   (11 ytiles of 6 rows, 4 oc-quarters)
    conv5x5_relu<32><<<BB * NYT * 4, 256, SMEMC>>>((const float*)ph, w0, b0, (float*)py1);
    conv5x5_relu<64><<<BB * NYT * 4, 256, SMEMC>>>((const float*)py1, w1, b1, (float*)py2);
    conv3k<<<BB * 16, 256, SMEM3>>>((const float*)py2, w2, b2, out);
}

// round 11
// speedup vs baseline: 1.2792x; 1.2792x over previous
#include <cuda_runtime.h>
#include <cstdint>
#include <cstddef>

// Problem constants (fixed by the reference)
#define BB 256
#define CC 32
#define HH 64
#define WW 64
#define PW 68           // padded width/height (2-px zero ring for 5x5 SAME)
#define PIMG (PW*PW)    // 4624

#define CHUNK 8                  // input channels per tile pass (= #warps)
#define TROWS 12                 // padded rows per tile (8 out + 4 halo)
#define CROWS (TROWS*PW)         // 816 floats per channel slab
#define TSZ   (CHUNK*CROWS)      // 6528 floats per tile copy

#define CHUNK3 16                // conv3k channel chunk

// ---------------------------------------------------------------------------
// Device-global scratch (allocation-free rule: __device__ globals only).
// ---------------------------------------------------------------------------
__device__ float g_h [(size_t)BB * CC * PIMG];   // rotated input, padded
__device__ float g_y1[(size_t)BB * 64 * PIMG];   // conv1 output, padded
__device__ float g_y2[(size_t)BB * 64 * PIMG];   // conv2 output, padded

// ---------------------------------------------------------------------------
// Packed dual-fp32 helper (full-rate fp32 path on Blackwell)
// ---------------------------------------------------------------------------
__device__ __forceinline__ void fma2(unsigned long long& d,
                                     unsigned long long a,
                                     unsigned long long b) {
    asm("fma.rn.f32x2 %0, %1, %2, %0;" : "+l"(d) : "l"(a), "l"(b));
}

// 16B broadcast load of two adjacent u64 weight duplicates.
__device__ __forceinline__ void lds_v2u64(unsigned long long& a,
                                          unsigned long long& b,
                                          const void* p) {
    unsigned int addr = (unsigned int)__cvta_generic_to_shared(p);
    asm("ld.shared.v2.u64 {%0, %1}, [%2];" : "=l"(a), "=l"(b) : "r"(addr));
}

// ---------------------------------------------------------------------------
// Kernel 1: rotation (separable because source rows are replicated).
// ---------------------------------------------------------------------------
__global__ void rotate_kernel(const float* __restrict__ xin,
                              float* __restrict__ hout)
{
    const int bc = blockIdx.x;          // b*32 + c
    const int c  = bc & (CC - 1);

    __shared__ float row[WW];
    if (threadIdx.x < WW) row[threadIdx.x] = xin[(size_t)bc * WW + threadIdx.x];
    __syncthreads();

    const float ang = (-180.0f / 32.0f) * (float)c * 0.017453292519943295f;
    float si, co;
    sincosf(ang, &si, &co);

    float* dst = hout + (size_t)bc * PIMG;
    for (int p = threadIdx.x; p < PIMG; p += blockDim.x) {
        const int py = p / PW;
        const int px = p - py * PW;
        const int y = py - 2, x = px - 2;
        float val = 0.f;
        if ((unsigned)y < 64u && (unsigned)x < 64u) {
            const float xx = (float)x - 31.5f;
            const float yy = (float)y - 31.5f;
            const float xs = co * xx + si * yy + 31.5f;
            const float ys = co * yy - si * xx + 31.5f;
            const float x0f = floorf(xs);
            const float y0f = floorf(ys);
            const int x0  = (int)x0f;
            const int y0i = (int)y0f;
            const float wx1 = xs - x0f, wx0 = 1.f - wx1;
            const float wy1 = ys - y0f, wy0 = 1.f - wy1;
            float fy = 0.f;
            if ((unsigned)y0i       < 64u) fy += wy0;
            if ((unsigned)(y0i + 1) < 64u) fy += wy1;
            float fx = 0.f;
            if ((unsigned)x0       < 64u) fx += wx0 * row[x0];
            if ((unsigned)(x0 + 1) < 64u) fx += wx1 * row[x0 + 1];
            val = fy * fx;
        }
        dst[p] = val;
    }
}

// ---------------------------------------------------------------------------
// Re-zero the padding rings of the conv scratch buffers each launch.
// ---------------------------------------------------------------------------
__global__ void zero_borders(float* __restrict__ a, float* __restrict__ b)
{
    const int bc = blockIdx.x;          // b*64 + ch
    float* pa = a + (size_t)bc * PIMG;
    float* pb = b + (size_t)bc * PIMG;
    for (int p = threadIdx.x; p < 528; p += blockDim.x) {
        int off;
        if (p < 136)        off = p;                         // rows 0,1
        else if (p < 272)   off = 66 * PW + (p - 136);       // rows 66,67
        else {
            const int q = p - 272;
            const int r = 2 + (q >> 2);                      // rows 2..65
            const int cc4 = q & 3;
            const int col = (cc4 < 2) ? cc4 : 64 + cc4;      // cols 0,1,66,67
            off = r * PW + col;
        }
        pa[off] = 0.f;
        pb[off] = 0.f;
    }
}

// ---------------------------------------------------------------------------
// 5x5 SAME conv, CIN -> 64, ReLU.  (R9 structure + LDS.128 weight broadcast)
// Grid = (image, 8-row ytile, oc-quarter). Block 256 thr = 8 warps.
//   warp w -> 2 output channels: ocq*16 + w*2 .. +2
//   lane l -> cols {2l,2l+1} as f32x2; 8 output rows per thread
// acc[2][8] u64; kx-outermost with 12 row-pairs register-cached (each pixel
// pair loaded once per kx, reused across ky). Weights interleaved [k][j0,j1]
// and duplicated, fetched as ONE 16B broadcast per (ky,kx) feeding both oc.
// smem: tileA (raw) + tileB (shifted 1 float; odd-kx pairs aligned).
// ---------------------------------------------------------------------------
template <int CIN>
__global__ void __launch_bounds__(256, 2)
conv5x5_relu(const float* __restrict__ in,    // [B][CIN][68][68]
             const float* __restrict__ w,     // [64][CIN][5][5]
             const float* __restrict__ bias,  // [64]
             float* __restrict__ out)         // [B][64][68][68]
{
    extern __shared__ float smem[];
    float*  tileA = smem;                      // TSZ floats
    float*  tileB = smem + TSZ;                // TSZ floats (shifted copy)
    float2* wsm   = (float2*)(smem + 2 * TSZ); // 8 warps x 2 bufs x 50 f2

    const int blk   = blockIdx.x;              // b*32 + ytile*4 + ocq
    const int ocq   = blk & 3;
    const int ytile = (blk >> 2) & 7;
    const int b     = blk >> 5;
    const int y0    = ytile * 8;

    const int warp   = threadIdx.x >> 5;
    const int lane   = threadIdx.x & 31;
    const int ocbase = ocq * 16 + warp * 2;

    // ---- hoisted weight-staging indexing (interleaved [k][j]) ----
    // warp's 50 floats: slot idx = k*2 + j  (idx = lane + it*32, <50)
    int  goff[2];
    bool act[2];
#pragma unroll
    for (int it = 0; it < 2; ++it) {
        const int idx = lane + it * 32;
        act[it] = (idx < 50);
        const int j = idx & 1;
        const int k = idx >> 1;
        goff[it] = act[it] ? (((ocbase + j) * CIN) * 25 + k) : 0;
    }
    float wreg[2];
#pragma unroll
    for (int it = 0; it < 2; ++it)
        wreg[it] = act[it] ? w[goff[it]] : 0.f;

    unsigned long long acc[2][8];
#pragma unroll
    for (int j = 0; j < 2; ++j)
#pragma unroll
        for (int yr = 0; yr < 8; ++yr) acc[j][yr] = 0ull;

    constexpr int NCHUNK = CIN / CHUNK;
#pragma unroll 1
    for (int chunk = 0; chunk < NCHUNK; ++chunk) {
        __syncthreads();   // previous chunk fully consumed
        // tile load: warp <-> channel; 816 floats per channel slab
        const float* srcc = in + ((size_t)b * CIN + chunk * CHUNK + warp) * PIMG
                               + (size_t)y0 * PW;
        const int ibase = warp * CROWS;
#pragma unroll
        for (int jj = 0; jj < 26; ++jj) {
            const int pos = lane + jj * 32;
            if (pos < CROWS) {
                const float v = srcc[pos];
                const int i = ibase + pos;
                tileA[i] = v;
                if (i) tileB[i - 1] = v;   // tileB col 67 never read
            }
        }
        __syncthreads();

#pragma unroll 1
        for (int cl = 0; cl < CHUNK; ++cl) {
            const int c = chunk * CHUNK + cl;

            // ---- stage prefetched weights (channel c), dup'd [k][j] ----
            float2* wb = wsm + (size_t)(warp * 2 + (c & 1)) * 50;
#pragma unroll
            for (int it = 0; it < 2; ++it) {
                const int idx = lane + it * 32;
                if (act[it]) wb[idx] = make_float2(wreg[it], wreg[it]);
            }
            __syncwarp();

            // ---- prefetch channel c+1 weights (pointer bump only) ----
            if (c + 1 < CIN) {
#pragma unroll
                for (int it = 0; it < 2; ++it)
                    if (act[it]) wreg[it] = w[goff[it] + (c + 1) * 25];
            }

            // ---- compute: kx-outermost, 12 row pairs cached in regs ----
            const float* ta = tileA + cl * CROWS + 2 * lane;
            const float* tb = tileB + cl * CROWS + 2 * lane;
            const unsigned long long* wu = (const unsigned long long*)wb;
#pragma unroll
            for (int kx = 0; kx < 5; ++kx) {
                const float* tsrc = (kx & 1) ? tb : ta;
                const int xoff = (kx >> 1) * 2;
                unsigned long long p[TROWS];
#pragma unroll
                for (int r = 0; r < TROWS; ++r)
                    p[r] = *(const unsigned long long*)(tsrc + r * PW + xoff);
#pragma unroll
                for (int ky = 0; ky < 5; ++ky) {
                    unsigned long long w0, w1;
                    lds_v2u64(w0, w1, wu + (ky * 5 + kx) * 2);
#pragma unroll
                    for (int yr = 0; yr < 8; ++yr) {
                        fma2(acc[0][yr], w0, p[ky + yr]);
                        fma2(acc[1][yr], w1, p[ky + yr]);
                    }
                }
            }
        }
    }

    // ---- epilogue: bias + ReLU, write padded interior ----
    const size_t ob = (size_t)b * 64;
#pragma unroll
    for (int j = 0; j < 2; ++j) {
        const int oc = ocbase + j;
        const float bv = bias[oc];
#pragma unroll
        for (int yr = 0; yr < 8; ++yr) {
            const float lo = __uint_as_float((unsigned)(acc[j][yr] & 0xffffffffull));
            const float hi = __uint_as_float((unsigned)(acc[j][yr] >> 32));
            float2 o;
            o.x = fmaxf(lo + bv, 0.f);
            o.y = fmaxf(hi + bv, 0.f);
            *(float2*)(out + (ob + oc) * PIMG
                           + (size_t)(y0 + 2 + yr) * PW + 2 + 2 * lane) = o;
        }
    }
}

// ---------------------------------------------------------------------------
// Final 5x5 conv, 64 -> 1, writes d_out (B,64,64). Channel-chunked smem,
// 4 blocks/SM.
// ---------------------------------------------------------------------------
__global__ void __launch_bounds__(256, 4)
conv3k(const float* __restrict__ in,   // [B][64][68][68]
       const float* __restrict__ w2,   // [1][64][5][5]
       const float* __restrict__ b2,   // [1]
       float* __restrict__ out)        // [B][64][64]
{
    extern __shared__ float smem[];
    float* tile = smem;                     // CHUNK3*8*68
    float* ws   = smem + CHUNK3 * 8 * PW;   // 1600

    const int blk   = blockIdx.x;
    const int ytile = blk & 15;
    const int b     = blk >> 4;
    const int y0    = ytile * 4;

    for (int i = threadIdx.x; i < 1600; i += 256) ws[i] = w2[i];

    const int yr = threadIdx.x >> 6;    // 0..3
    const int x  = threadIdx.x & 63;    // 0..63
    float acc = b2[0];

#pragma unroll 1
    for (int chunk = 0; chunk < 64 / CHUNK3; ++chunk) {
        __syncthreads();
        const float* src = in + ((size_t)b * 64 + chunk * CHUNK3) * PIMG
                              + (size_t)y0 * PW;
        for (int i = threadIdx.x; i < CHUNK3 * 8 * PW; i += 256) {
            const int ch = i / (8 * PW);
            const int r  = i - ch * (8 * PW);
            tile[i] = src[(size_t)ch * PIMG + r];
        }
        __syncthreads();

#pragma unroll 1
        for (int cl = 0; cl < CHUNK3; ++cl) {
            const float* t  = tile + cl * (8 * PW) + yr * PW + x;
            const float* wc = ws + (chunk * CHUNK3 + cl) * 25;
#pragma unroll
            for (int ky = 0; ky < 5; ++ky)
#pragma unroll
                for (int kx = 0; kx < 5; ++kx)
                    acc += wc[ky * 5 + kx] * t[ky * PW + kx];
        }
    }
    out[(size_t)b * 4096 + (size_t)(y0 + yr) * 64 + x] = acc;
}

// ---------------------------------------------------------------------------
// kernel_launch (graph-capturable: kernel launches + non-stream queries only)
// Input order per metadata: x, w0, b0, w1, b1, w2, b2 (all fp32).
// ---------------------------------------------------------------------------
extern "C" void kernel_launch(void* const* d_in, const int* in_sizes, int n_in,
                              void* d_out, int out_size)
{
    (void)in_sizes; (void)n_in; (void)out_size;

    const float* x  = (const float*)d_in[0];
    const float* w0 = (const float*)d_in[1];
    const float* b0 = (const float*)d_in[2];
    const float* w1 = (const float*)d_in[3];
    const float* b1 = (const float*)d_in[4];
    const float* w2 = (const float*)d_in[5];
    const float* b2 = (const float*)d_in[6];
    float* out = (float*)d_out;

    void *ph, *py1, *py2;
    cudaGetSymbolAddress(&ph,  g_h);
    cudaGetSymbolAddress(&py1, g_y1);
    cudaGetSymbolAddress(&py2, g_y2);

    // tileA + tileB + per-warp weight double buffers (50 f2 x 2 x 8 warps)
    constexpr int SMEMC = (2 * TSZ) * 4 + 8 * 2 * 50 * 8;    // 58,624 B
    constexpr int SMEM3 = (CHUNK3 * 8 * PW + 1600) * 4;      // 41,216 B

    cudaFuncSetAttribute(conv5x5_relu<32>,
                         cudaFuncAttributeMaxDynamicSharedMemorySize, SMEMC);
    cudaFuncSetAttribute(conv5x5_relu<64>,
                         cudaFuncAttributeMaxDynamicSharedMemorySize, SMEMC);
    cudaFuncSetAttribute(conv3k,
                         cudaFuncAttributeMaxDynamicSharedMemorySize, SMEM3);

    rotate_kernel<<<BB * CC, 128>>>(x, (float*)ph);
    zero_borders<<<BB * 64, 128>>>((float*)py1, (float*)py2);
    // grid: b*32 + ytile*4 + ocq   (8 ytiles of 8 rows, 4 oc-quarters)
    conv5x5_relu<32><<<BB * 32, 256, SMEMC>>>((const float*)ph, w0, b0, (float*)py1);
    conv5x5_relu<64><<<BB * 32, 256, SMEMC>>>((const float*)py1, w1, b1, (float*)py2);
    conv3k<<<BB * 16, 256, SMEM3>>>((const float*)py2, w2, b2, out);
}

// round 14
// speedup vs baseline: 1.6129x; 1.2608x over previous
#include <cuda_runtime.h>
#include <cuda_bf16.h>
#include <cstdint>
#include <cstddef>

// Problem constants (fixed by the reference)
#define BB 256
#define CC 32
#define HH 64
#define WW 64
#define PW 68           // padded width/height (2-px zero ring for 5x5 SAME)
#define PIMG (PW*PW)    // 4624

// scalar conv1 tiling (R11 config)
#define CHUNK 8
#define TROWS 12
#define CROWS (TROWS*PW)
#define TSZ   (CHUNK*CROWS)

#define CHUNK3 16                // conv3k channel chunk

// conv2 HMMA tiling
#define NPT2 35                  // 128-pixel tiles covering [128, 4608)
#define AR2  404                 // A tile rows: 128 + 2*138 halo
#define ASTR 36                  // padded row stride in u32 (conflict-free)
// smem word offsets
#define WOFF_A0 64
#define WOFF_A1 (64 + AR2*ASTR)
#define WOFF_B  (64 + 2*AR2*ASTR)
#define SMEM2_BYTES ((WOFF_B + 2*64*ASTR) * 4)   // 135,040 B

// ---------------------------------------------------------------------------
// Device-global scratch (allocation-free rule: __device__ globals only).
// ---------------------------------------------------------------------------
__device__ float    g_h  [(size_t)BB * CC * PIMG];   // rotated input, padded
__device__ float    g_y1 [(size_t)BB * 64 * PIMG];   // conv1 output, padded
__device__ float    g_y2 [(size_t)BB * 64 * PIMG];   // conv2 output, padded
__device__ unsigned g_ahi[(size_t)BB * PIMG * 32];   // X^T hi: [b][pix][cin/2]
__device__ unsigned g_alo[(size_t)BB * PIMG * 32];   // X^T lo
__device__ unsigned g_wbf[2 * 25 * 64 * 32];         // W: [split][pos][oc][cin/2]

// ---------------------------------------------------------------------------
// Helpers
// ---------------------------------------------------------------------------
__device__ __forceinline__ void fma2(unsigned long long& d,
                                     unsigned long long a,
                                     unsigned long long b) {
    asm("fma.rn.f32x2 %0, %1, %2, %0;" : "+l"(d) : "l"(a), "l"(b));
}

__device__ __forceinline__ void lds_v2u64(unsigned long long& a,
                                          unsigned long long& b,
                                          const void* p) {
    unsigned int addr = (unsigned int)__cvta_generic_to_shared(p);
    asm("ld.shared.v2.u64 {%0, %1}, [%2];" : "=l"(a), "=l"(b) : "r"(addr));
}

// Ampere-lineage bf16 tensor-core MMA (ISA-portable, valid on sm_100 target).
__device__ __forceinline__ void mma_bf16(float* c,
                                         unsigned a0, unsigned a1,
                                         unsigned a2, unsigned a3,
                                         unsigned b0, unsigned b1) {
    asm volatile(
        "mma.sync.aligned.m16n8k16.row.col.f32.bf16.bf16.f32 "
        "{%0,%1,%2,%3}, {%4,%5,%6,%7}, {%8,%9}, {%0,%1,%2,%3};"
        : "+f"(c[0]), "+f"(c[1]), "+f"(c[2]), "+f"(c[3])
        : "r"(a0), "r"(a1), "r"(a2), "r"(a3), "r"(b0), "r"(b1));
}

// ---------------------------------------------------------------------------
// Kernel 1: rotation (separable because source rows are replicated).
// ---------------------------------------------------------------------------
__global__ void rotate_kernel(const float* __restrict__ xin,
                              float* __restrict__ hout)
{
    const int bc = blockIdx.x;
    const int c  = bc & (CC - 1);

    __shared__ float row[WW];
    if (threadIdx.x < WW) row[threadIdx.x] = xin[(size_t)bc * WW + threadIdx.x];
    __syncthreads();

    const float ang = (-180.0f / 32.0f) * (float)c * 0.017453292519943295f;
    float si, co;
    sincosf(ang, &si, &co);

    float* dst = hout + (size_t)bc * PIMG;
    for (int p = threadIdx.x; p < PIMG; p += blockDim.x) {
        const int py = p / PW;
        const int px = p - py * PW;
        const int y = py - 2, x = px - 2;
        float val = 0.f;
        if ((unsigned)y < 64u && (unsigned)x < 64u) {
            const float xx = (float)x - 31.5f;
            const float yy = (float)y - 31.5f;
            const float xs = co * xx + si * yy + 31.5f;
            const float ys = co * yy - si * xx + 31.5f;
            const float x0f = floorf(xs);
            const float y0f = floorf(ys);
            const int x0  = (int)x0f;
            const int y0i = (int)y0f;
            const float wx1 = xs - x0f, wx0 = 1.f - wx1;
            const float wy1 = ys - y0f, wy0 = 1.f - wy1;
            float fy = 0.f;
            if ((unsigned)y0i       < 64u) fy += wy0;
            if ((unsigned)(y0i + 1) < 64u) fy += wy1;
            float fx = 0.f;
            if ((unsigned)x0       < 64u) fx += wx0 * row[x0];
            if ((unsigned)(x0 + 1) < 64u) fx += wx1 * row[x0 + 1];
            val = fy * fx;
        }
        dst[p] = val;
    }
}

// ---------------------------------------------------------------------------
// Re-zero the padding rings of the conv scratch buffers each launch.
// ---------------------------------------------------------------------------
__global__ void zero_borders(float* __restrict__ a, float* __restrict__ b)
{
    const int bc = blockIdx.x;
    float* pa = a + (size_t)bc * PIMG;
    float* pb = b + (size_t)bc * PIMG;
    for (int p = threadIdx.x; p < 528; p += blockDim.x) {
        int off;
        if (p < 136)        off = p;
        else if (p < 272)   off = 66 * PW + (p - 136);
        else {
            const int q = p - 272;
            const int r = 2 + (q >> 2);
            const int cc4 = q & 3;
            const int col = (cc4 < 2) ? cc4 : 64 + cc4;
            off = r * PW + col;
        }
        pa[off] = 0.f;
        pb[off] = 0.f;
    }
}

// ---------------------------------------------------------------------------
// Scalar 5x5 conv (conv1 only), R11 structure.
// ---------------------------------------------------------------------------
template <int CIN>
__global__ void __launch_bounds__(256, 2)
conv5x5_relu(const float* __restrict__ in,
             const float* __restrict__ w,
             const float* __restrict__ bias,
             float* __restrict__ out)
{
    extern __shared__ float smem[];
    float*  tileA = smem;
    float*  tileB = smem + TSZ;
    float2* wsm   = (float2*)(smem + 2 * TSZ);

    const int blk   = blockIdx.x;
    const int ocq   = blk & 3;
    const int ytile = (blk >> 2) & 7;
    const int b     = blk >> 5;
    const int y0    = ytile * 8;

    const int warp   = threadIdx.x >> 5;
    const int lane   = threadIdx.x & 31;
    const int ocbase = ocq * 16 + warp * 2;

    int  goff[2];
    bool act[2];
#pragma unroll
    for (int it = 0; it < 2; ++it) {
        const int idx = lane + it * 32;
        act[it] = (idx < 50);
        const int j = idx & 1;
        const int k = idx >> 1;
        goff[it] = act[it] ? (((ocbase + j) * CIN) * 25 + k) : 0;
    }
    float wreg[2];
#pragma unroll
    for (int it = 0; it < 2; ++it)
        wreg[it] = act[it] ? w[goff[it]] : 0.f;

    unsigned long long acc[2][8];
#pragma unroll
    for (int j = 0; j < 2; ++j)
#pragma unroll
        for (int yr = 0; yr < 8; ++yr) acc[j][yr] = 0ull;

    constexpr int NCHUNK = CIN / CHUNK;
#pragma unroll 1
    for (int chunk = 0; chunk < NCHUNK; ++chunk) {
        __syncthreads();
        const float* srcc = in + ((size_t)b * CIN + chunk * CHUNK + warp) * PIMG
                               + (size_t)y0 * PW;
        const int ibase = warp * CROWS;
#pragma unroll
        for (int jj = 0; jj < 26; ++jj) {
            const int pos = lane + jj * 32;
            if (pos < CROWS) {
                const float v = srcc[pos];
                const int i = ibase + pos;
                tileA[i] = v;
                if (i) tileB[i - 1] = v;
            }
        }
        __syncthreads();

#pragma unroll 1
        for (int cl = 0; cl < CHUNK; ++cl) {
            const int c = chunk * CHUNK + cl;

            float2* wb = wsm + (size_t)(warp * 2 + (c & 1)) * 50;
#pragma unroll
            for (int it = 0; it < 2; ++it) {
                const int idx = lane + it * 32;
                if (act[it]) wb[idx] = make_float2(wreg[it], wreg[it]);
            }
            __syncwarp();

            if (c + 1 < CIN) {
#pragma unroll
                for (int it = 0; it < 2; ++it)
                    if (act[it]) wreg[it] = w[goff[it] + (c + 1) * 25];
            }

            const float* ta = tileA + cl * CROWS + 2 * lane;
            const float* tb = tileB + cl * CROWS + 2 * lane;
            const unsigned long long* wu = (const unsigned long long*)wb;
#pragma unroll
            for (int kx = 0; kx < 5; ++kx) {
                const float* tsrc = (kx & 1) ? tb : ta;
                const int xoff = (kx >> 1) * 2;
                unsigned long long p[TROWS];
#pragma unroll
                for (int r = 0; r < TROWS; ++r)
                    p[r] = *(const unsigned long long*)(tsrc + r * PW + xoff);
#pragma unroll
                for (int ky = 0; ky < 5; ++ky) {
                    unsigned long long w0, w1;
                    lds_v2u64(w0, w1, wu + (ky * 5 + kx) * 2);
#pragma unroll
                    for (int yr = 0; yr < 8; ++yr) {
                        fma2(acc[0][yr], w0, p[ky + yr]);
                        fma2(acc[1][yr], w1, p[ky + yr]);
                    }
                }
            }
        }
    }

    const size_t ob = (size_t)b * 64;
#pragma unroll
    for (int j = 0; j < 2; ++j) {
        const int oc = ocbase + j;
        const float bv = bias[oc];
#pragma unroll
        for (int yr = 0; yr < 8; ++yr) {
            const float lo = __uint_as_float((unsigned)(acc[j][yr] & 0xffffffffull));
            const float hi = __uint_as_float((unsigned)(acc[j][yr] >> 32));
            float2 o;
            o.x = fmaxf(lo + bv, 0.f);
            o.y = fmaxf(hi + bv, 0.f);
            *(float2*)(out + (ob + oc) * PIMG
                           + (size_t)(y0 + 2 + yr) * PW + 2 + 2 * lane) = o;
        }
    }
}

// ---------------------------------------------------------------------------
// Weight pack for conv2 MMA: w1[oc][cin][ky][kx] fp32 ->
// g_wbf[split][pos][oc][cin] bf16 (hi/lo split), cin pairs packed in uint.
// ---------------------------------------------------------------------------
__global__ void wprep_kernel(const float* __restrict__ w1)
{
    const int pos = blockIdx.x;     // 0..24
    for (int i = threadIdx.x; i < 2048; i += blockDim.x) {
        const int oc = i >> 5;             // 0..63
        const int cp = i & 31;             // cin pair
        const int c0 = 2 * cp, c1 = 2 * cp + 1;
        const float v0 = w1[((size_t)oc * 64 + c0) * 25 + pos];
        const float v1 = w1[((size_t)oc * 64 + c1) * 25 + pos];
        __nv_bfloat16 h0 = __float2bfloat16(v0);
        __nv_bfloat16 h1 = __float2bfloat16(v1);
        __nv_bfloat16 l0 = __float2bfloat16(v0 - __bfloat162float(h0));
        __nv_bfloat16 l1 = __float2bfloat16(v1 - __bfloat162float(h1));
        const unsigned hp = (unsigned)__bfloat16_as_ushort(h0)
                          | ((unsigned)__bfloat16_as_ushort(h1) << 16);
        const unsigned lp = (unsigned)__bfloat16_as_ushort(l0)
                          | ((unsigned)__bfloat16_as_ushort(l1) << 16);
        g_wbf[(0 * 25 + pos) * 2048 + i] = hp;
        g_wbf[(1 * 25 + pos) * 2048 + i] = lp;
    }
}

// ---------------------------------------------------------------------------
// Transpose + bf16-split: g_y1[b][cin][pix] fp32 -> g_ahi/g_alo[b][pix][cin].
// ---------------------------------------------------------------------------
__global__ void asplit_kernel(const float* __restrict__ y1)
{
    __shared__ float stage[64 * 69];
    const int b = blockIdx.x / PW;
    const int y = blockIdx.x - b * PW;

    for (int i = threadIdx.x; i < 64 * PW; i += blockDim.x) {
        const int cin = i / PW;
        const int px  = i - cin * PW;
        stage[cin * 69 + px] = y1[((size_t)b * 64 + cin) * PIMG + y * PW + px];
    }
    __syncthreads();

    for (int i = threadIdx.x; i < PW * 32; i += blockDim.x) {
        const int px = i >> 5;
        const int cp = i & 31;
        const float v0 = stage[(2 * cp) * 69 + px];
        const float v1 = stage[(2 * cp + 1) * 69 + px];
        __nv_bfloat16 h0 = __float2bfloat16(v0);
        __nv_bfloat16 h1 = __float2bfloat16(v1);
        __nv_bfloat16 l0 = __float2bfloat16(v0 - __bfloat162float(h0));
        __nv_bfloat16 l1 = __float2bfloat16(v1 - __bfloat162float(h1));
        const size_t o = ((size_t)b * PIMG + y * PW + px) * 32 + cp;
        g_ahi[o] = (unsigned)__bfloat16_as_ushort(h0)
                 | ((unsigned)__bfloat16_as_ushort(h1) << 16);
        g_alo[o] = (unsigned)__bfloat16_as_ushort(l0)
                 | ((unsigned)__bfloat16_as_ushort(l1) << 16);
    }
}

// ---------------------------------------------------------------------------
// conv2 via mma.sync (bf16 hi/lo split, fp32 acc in registers).
// CTA = 128 pixels x 64 oc. Warp w -> pixels [P0+16w, +16) (one m16 tile),
// 8 n8 tiles (oc 0..63), acc[8][4]. 25 positions x 3 splits x 4 k-steps.
// smem: A[2][404 rows][36 u32] (row pad -> conflict-free fragment LDS) +
//       B[2][64][36] staged per pos with register prefetch.
// ---------------------------------------------------------------------------
__global__ void __launch_bounds__(256, 1)
conv2_hmma(const unsigned* __restrict__ ahi,   // [B][4624][32]
           const unsigned* __restrict__ alo,
           const unsigned* __restrict__ wbf,   // [2][25][64][32]
           const float* __restrict__ bias,     // [64]
           float* __restrict__ out)            // g_y2 [B][64][4624]
{
    extern __shared__ float smem[];
    float*    sbias = smem;
    unsigned* sA    = (unsigned*)smem + WOFF_A0;   // [2][AR2][ASTR]
    unsigned* sB    = (unsigned*)smem + WOFF_B;    // [2][64][ASTR]

    const int tid  = threadIdx.x;
    const int wid  = tid >> 5;
    const int lane = tid & 31;
    const int g    = lane >> 2;
    const int t    = lane & 3;

    const int b  = blockIdx.x / NPT2;
    const int tt = blockIdx.x - b * NPT2;
    const int P0 = 128 + 128 * tt;

    if (tid < 64) sbias[tid] = bias[tid];

    // ---- load A tile (both splits): rows P0-138 .. P0+265, zero-guarded ----
#pragma unroll 1
    for (int sp = 0; sp < 2; ++sp) {
        const uint4* src = (const uint4*)((sp ? alo : ahi) + (size_t)b * PIMG * 32);
        unsigned* dst = sA + sp * (AR2 * ASTR);
#pragma unroll 1
        for (int i = tid; i < AR2 * 8; i += 256) {
            const int r = i >> 3, q4 = i & 7;
            const int p = P0 - 138 + r;
            uint4 v = make_uint4(0, 0, 0, 0);
            if (p >= 0 && p < PIMG) v = src[(size_t)p * 8 + q4];
            *(uint4*)(dst + r * ASTR + 4 * q4) = v;
        }
    }

    float acc[8][4];
#pragma unroll
    for (int n8 = 0; n8 < 8; ++n8)
#pragma unroll
        for (int j = 0; j < 4; ++j) acc[n8][j] = 0.f;

    // ---- B prefetch regs: 4 uint4 per thread covering [2][64][32] u32 ----
    const uint4* wq = (const uint4*)wbf;
    uint4 vr[4];
#pragma unroll
    for (int j = 0; j < 4; ++j) {
        const int i = tid + j * 256;
        const int s = i >> 9, rr = i & 511;
        vr[j] = wq[(size_t)(s * 25 + 0) * 512 + rr];
    }

    const int baserow = wid * 16;

#pragma unroll 1
    for (int pos = 0; pos < 25; ++pos) {
        __syncthreads();   // previous compute done reading sB
#pragma unroll
        for (int j = 0; j < 4; ++j) {
            const int i = tid + j * 256;
            const int s = i >> 9, rr = i & 511;
            *(uint4*)(sB + s * (64 * ASTR) + (rr >> 3) * ASTR + 4 * (rr & 7)) = vr[j];
        }
        __syncthreads();
        if (pos < 24) {
#pragma unroll
            for (int j = 0; j < 4; ++j) {
                const int i = tid + j * 256;
                const int s = i >> 9, rr = i & 511;
                vr[j] = wq[(size_t)(s * 25 + pos + 1) * 512 + rr];
            }
        }

        const int ky = pos / 5, kx = pos - 5 * ky;
        const int rowoff = 138 + (ky - 2) * PW + (kx - 2);
        const int arow = baserow + rowoff + g;

#pragma unroll
        for (int s = 0; s < 3; ++s) {
            // splits: 0: Ah*Bh, 1: Ah*Bl, 2: Al*Bh
            const unsigned* As = sA + ((s == 2) ? AR2 * ASTR : 0);
            const unsigned* Bs = sB + ((s == 1) ? 64 * ASTR : 0);
#pragma unroll
            for (int kk = 0; kk < 4; ++kk) {
                const unsigned* ab = As + arow * ASTR + 8 * kk + t;
                const unsigned a0 = ab[0];
                const unsigned a1 = ab[8 * ASTR];
                const unsigned a2 = ab[4];
                const unsigned a3 = ab[8 * ASTR + 4];
#pragma unroll
                for (int n8 = 0; n8 < 8; ++n8) {
                    const unsigned* bb = Bs + (n8 * 8 + g) * ASTR + 8 * kk + t;
                    mma_bf16(acc[n8], a0, a1, a2, a3, bb[0], bb[4]);
                }
            }
        }
    }

    // ---- epilogue: bias + ReLU, interior pixels only ----
    const int p_lo = P0 + wid * 16 + g;
    const int p_hi = p_lo + 8;
    const int ylo = p_lo / PW, xlo = p_lo - ylo * PW;
    const int yhi = p_hi / PW, xhi = p_hi - yhi * PW;
    const bool v_lo = (ylo >= 2 && ylo < 66 && xlo >= 2 && xlo < 66);
    const bool v_hi = (yhi >= 2 && yhi < 66 && xhi >= 2 && xhi < 66);
    float* ob = out + (size_t)b * 64 * PIMG;
#pragma unroll
    for (int n8 = 0; n8 < 8; ++n8) {
        const int oc = n8 * 8 + 2 * t;
        const float bv0 = sbias[oc], bv1 = sbias[oc + 1];
        if (v_lo) {
            ob[(size_t)oc * PIMG + p_lo]       = fmaxf(acc[n8][0] + bv0, 0.f);
            ob[(size_t)(oc + 1) * PIMG + p_lo] = fmaxf(acc[n8][1] + bv1, 0.f);
        }
        if (v_hi) {
            ob[(size_t)oc * PIMG + p_hi]       = fmaxf(acc[n8][2] + bv0, 0.f);
            ob[(size_t)(oc + 1) * PIMG + p_hi] = fmaxf(acc[n8][3] + bv1, 0.f);
        }
    }
}

// ---------------------------------------------------------------------------
// Final 5x5 conv, 64 -> 1, writes d_out (B,64,64).
// ---------------------------------------------------------------------------
__global__ void __launch_bounds__(256, 4)
conv3k(const float* __restrict__ in,
       const float* __restrict__ w2,
       const float* __restrict__ b2,
       float* __restrict__ out)
{
    extern __shared__ float smem[];
    float* tile = smem;
    float* ws   = smem + CHUNK3 * 8 * PW;

    const int blk   = blockIdx.x;
    const int ytile = blk & 15;
    const int b     = blk >> 4;
    const int y0    = ytile * 4;

    for (int i = threadIdx.x; i < 1600; i += 256) ws[i] = w2[i];

    const int yr = threadIdx.x >> 6;
    const int x  = threadIdx.x & 63;
    float acc = b2[0];

#pragma unroll 1
    for (int chunk = 0; chunk < 64 / CHUNK3; ++chunk) {
        __syncthreads();
        const float* src = in + ((size_t)b * 64 + chunk * CHUNK3) * PIMG
                              + (size_t)y0 * PW;
        for (int i = threadIdx.x; i < CHUNK3 * 8 * PW; i += 256) {
            const int ch = i / (8 * PW);
            const int r  = i - ch * (8 * PW);
            tile[i] = src[(size_t)ch * PIMG + r];
        }
        __syncthreads();

#pragma unroll 1
        for (int cl = 0; cl < CHUNK3; ++cl) {
            const float* t  = tile + cl * (8 * PW) + yr * PW + x;
            const float* wc = ws + (chunk * CHUNK3 + cl) * 25;
#pragma unroll
            for (int ky = 0; ky < 5; ++ky)
#pragma unroll
                for (int kx = 0; kx < 5; ++kx)
                    acc += wc[ky * 5 + kx] * t[ky * PW + kx];
        }
    }
    out[(size_t)b * 4096 + (size_t)(y0 + yr) * 64 + x] = acc;
}

// ---------------------------------------------------------------------------
// kernel_launch (graph-capturable)
// ---------------------------------------------------------------------------
extern "C" void kernel_launch(void* const* d_in, const int* in_sizes, int n_in,
                              void* d_out, int out_size)
{
    (void)in_sizes; (void)n_in; (void)out_size;

    const float* x  = (const float*)d_in[0];
    const float* w0 = (const float*)d_in[1];
    const float* b0 = (const float*)d_in[2];
    const float* w1 = (const float*)d_in[3];
    const float* b1 = (const float*)d_in[4];
    const float* w2 = (const float*)d_in[5];
    const float* b2 = (const float*)d_in[6];
    float* out = (float*)d_out;

    void *ph, *py1, *py2, *pahi, *palo, *pwbf;
    cudaGetSymbolAddress(&ph,   g_h);
    cudaGetSymbolAddress(&py1,  g_y1);
    cudaGetSymbolAddress(&py2,  g_y2);
    cudaGetSymbolAddress(&pahi, g_ahi);
    cudaGetSymbolAddress(&palo, g_alo);
    cudaGetSymbolAddress(&pwbf, g_wbf);

    constexpr int SMEMC = (2 * TSZ) * 4 + 8 * 2 * 50 * 8;    // 58,624 B
    constexpr int SMEM3 = (CHUNK3 * 8 * PW + 1600) * 4;      // 41,216 B

    cudaFuncSetAttribute(conv5x5_relu<32>,
                         cudaFuncAttributeMaxDynamicSharedMemorySize, SMEMC);
    cudaFuncSetAttribute(conv2_hmma,
                         cudaFuncAttributeMaxDynamicSharedMemorySize, SMEM2_BYTES);
    cudaFuncSetAttribute(conv3k,
                         cudaFuncAttributeMaxDynamicSharedMemorySize, SMEM3);

    rotate_kernel<<<BB * CC, 128>>>(x, (float*)ph);
    zero_borders<<<BB * 64, 128>>>((float*)py1, (float*)py2);
    wprep_kernel<<<25, 256>>>(w1);
    conv5x5_relu<32><<<BB * 32, 256, SMEMC>>>((const float*)ph, w0, b0, (float*)py1);
    asplit_kernel<<<BB * PW, 256>>>((const float*)py1);
    conv2_hmma<<<BB * NPT2, 256, SMEM2_BYTES>>>((const unsigned*)pahi,
                                                (const unsigned*)palo,
                                                (const unsigned*)pwbf, b1,
                                                (float*)py2);
    conv3k<<<BB * 16, 256, SMEM3>>>((const float*)py2, w2, b2, out);
}

// round 15
// speedup vs baseline: 2.0628x; 1.2790x over previous
#include <cuda_runtime.h>
#include <cuda_bf16.h>
#include <cstdint>
#include <cstddef>

// Problem constants (fixed by the reference)
#define BB 256
#define CC 32
#define HH 64
#define WW 64
#define PW 68           // padded width/height (2-px zero ring for 5x5 SAME)
#define PIMG (PW*PW)    // 4624

#define CHUNK3 16       // conv3k channel chunk

// conv HMMA tiling
#define NPT2 35         // 128-pixel tiles covering [128, 4608)
#define AR2  404        // A tile rows: 128 + 2*138 halo

// ---------------------------------------------------------------------------
// Device-global scratch (allocation-free rule: __device__ globals only).
// ---------------------------------------------------------------------------
__device__ float    g_y2  [(size_t)BB * 64 * PIMG];   // conv2 output, padded
__device__ unsigned g_ahi0[(size_t)BB * PIMG * 16];   // rotate out hi [b][pix][c/2]
__device__ unsigned g_alo0[(size_t)BB * PIMG * 16];   // rotate out lo
__device__ unsigned g_ahi [(size_t)BB * PIMG * 32];   // conv1 out hi  [b][pix][c/2]
__device__ unsigned g_alo [(size_t)BB * PIMG * 32];   // conv1 out lo
__device__ unsigned g_wbf0[2 * 25 * 64 * 16];         // w0: [split][pos][oc][cin/2]
__device__ unsigned g_wbf1[2 * 25 * 64 * 32];         // w1: [split][pos][oc][cin/2]

// ---------------------------------------------------------------------------
// Helpers
// ---------------------------------------------------------------------------
// Ampere-lineage bf16 tensor-core MMA (ISA-portable, valid on sm_100 target).
__device__ __forceinline__ void mma_bf16(float* c,
                                         unsigned a0, unsigned a1,
                                         unsigned a2, unsigned a3,
                                         unsigned b0, unsigned b1) {
    asm volatile(
        "mma.sync.aligned.m16n8k16.row.col.f32.bf16.bf16.f32 "
        "{%0,%1,%2,%3}, {%4,%5,%6,%7}, {%8,%9}, {%0,%1,%2,%3};"
        : "+f"(c[0]), "+f"(c[1]), "+f"(c[2]), "+f"(c[3])
        : "r"(a0), "r"(a1), "r"(a2), "r"(a3), "r"(b0), "r"(b1));
}

__device__ __forceinline__ unsigned pack_split_hi(float v0, float v1) {
    __nv_bfloat16 h0 = __float2bfloat16(v0);
    __nv_bfloat16 h1 = __float2bfloat16(v1);
    return (unsigned)__bfloat16_as_ushort(h0)
         | ((unsigned)__bfloat16_as_ushort(h1) << 16);
}
__device__ __forceinline__ unsigned pack_split_lo(float v0, float v1) {
    __nv_bfloat16 h0 = __float2bfloat16(v0);
    __nv_bfloat16 h1 = __float2bfloat16(v1);
    __nv_bfloat16 l0 = __float2bfloat16(v0 - __bfloat162float(h0));
    __nv_bfloat16 l1 = __float2bfloat16(v1 - __bfloat162float(h1));
    return (unsigned)__bfloat16_as_ushort(l0)
         | ((unsigned)__bfloat16_as_ushort(l1) << 16);
}

// ---------------------------------------------------------------------------
// Kernel 1: rotation -> bf16 hi/lo split, PIXEL-MAJOR [b][pix][16 words].
// Block = (b, padded row py). Separable bilinear (source rows replicated).
// Writes the full padded image (ring = 0), so no ring pass needed for conv1.
// ---------------------------------------------------------------------------
__global__ void rotate_kernel(const float* __restrict__ xin,
                              unsigned* __restrict__ ahi0,
                              unsigned* __restrict__ alo0)
{
    __shared__ float rows[CC * WW];     // x[b,0,c,:] for all 32 channels
    __shared__ float cosv[CC], sinv[CC];

    const int b  = blockIdx.x / PW;
    const int py = blockIdx.x - b * PW;
    const int tid = threadIdx.x;

    for (int i = tid; i < CC * WW; i += 256)
        rows[i] = xin[(size_t)b * (CC * WW) + i];
    if (tid < CC) {
        const float ang = (-180.0f / 32.0f) * (float)tid * 0.017453292519943295f;
        sincosf(ang, &sinv[tid], &cosv[tid]);
    }
    __syncthreads();

    const int y = py - 2;
    const float yy = (float)y - 31.5f;

    for (int i = tid; i < PW * 16; i += 256) {
        const int px = i >> 4;
        const int cp = i & 15;
        const int x = px - 2;
        float v[2];
#pragma unroll
        for (int j = 0; j < 2; ++j) {
            const int c = 2 * cp + j;
            float val = 0.f;
            if ((unsigned)y < 64u && (unsigned)x < 64u) {
                const float co = cosv[c], si = sinv[c];
                const float xx = (float)x - 31.5f;
                const float xs = co * xx + si * yy + 31.5f;
                const float ys = co * yy - si * xx + 31.5f;
                const float x0f = floorf(xs);
                const float y0f = floorf(ys);
                const int x0  = (int)x0f;
                const int y0i = (int)y0f;
                const float wx1 = xs - x0f, wx0 = 1.f - wx1;
                const float wy1 = ys - y0f, wy0 = 1.f - wy1;
                float fy = 0.f;
                if ((unsigned)y0i       < 64u) fy += wy0;
                if ((unsigned)(y0i + 1) < 64u) fy += wy1;
                float fx = 0.f;
                if ((unsigned)x0       < 64u) fx += wx0 * rows[c * WW + x0];
                if ((unsigned)(x0 + 1) < 64u) fx += wx1 * rows[c * WW + x0 + 1];
                val = fy * fx;
            }
            v[j] = val;
        }
        const size_t o = ((size_t)b * PIMG + py * PW + px) * 16 + cp;
        ahi0[o] = pack_split_hi(v[0], v[1]);
        alo0[o] = pack_split_lo(v[0], v[1]);
    }
}

// ---------------------------------------------------------------------------
// Ring zeroing: g_ahi/g_alo (pixel-major, 32 words/pixel) per image.
// ---------------------------------------------------------------------------
__device__ __forceinline__ int ring_off(int p) {
    int off;
    if (p < 136)        off = p;                         // rows 0,1
    else if (p < 272)   off = 66 * PW + (p - 136);       // rows 66,67
    else {
        const int q = p - 272;
        const int r = 2 + (q >> 2);                      // rows 2..65
        const int cc4 = q & 3;
        off = r * PW + ((cc4 < 2) ? cc4 : 64 + cc4);     // cols 0,1,66,67
    }
    return off;
}

__global__ void zb_a(unsigned* __restrict__ hi, unsigned* __restrict__ lo)
{
    const int b = blockIdx.x;
    for (int i = threadIdx.x; i < 528 * 32; i += 256) {
        const int pi = i >> 5, w = i & 31;
        const size_t o = ((size_t)b * PIMG + ring_off(pi)) * 32 + w;
        hi[o] = 0u;
        lo[o] = 0u;
    }
}

// Ring zeroing for g_y2 (channel-major fp32).
__global__ void zb_y2(float* __restrict__ a)
{
    const int bc = blockIdx.x;          // b*64 + ch
    float* pa = a + (size_t)bc * PIMG;
    for (int p = threadIdx.x; p < 528; p += blockDim.x)
        pa[ring_off(p)] = 0.f;
}

// ---------------------------------------------------------------------------
// Weight pack: w[oc][cin][5][5] fp32 -> [split][pos][oc][cin/2 words] bf16
// hi/lo split, cin pairs packed per uint.
// ---------------------------------------------------------------------------
template <int CIN>
__global__ void wprep_kernel(const float* __restrict__ w, unsigned* __restrict__ dst)
{
    constexpr int KW = CIN / 2;
    const int pos = blockIdx.x;     // 0..24
    for (int i = threadIdx.x; i < 64 * KW; i += blockDim.x) {
        const int oc = i / KW;
        const int cp = i - oc * KW;
        const float v0 = w[((size_t)oc * CIN + 2 * cp)     * 25 + pos];
        const float v1 = w[((size_t)oc * CIN + 2 * cp + 1) * 25 + pos];
        dst[(0 * 25 + pos) * (64 * KW) + i] = pack_split_hi(v0, v1);
        dst[(1 * 25 + pos) * (64 * KW) + i] = pack_split_lo(v0, v1);
    }
}

// ---------------------------------------------------------------------------
// 5x5 conv via mma.sync (bf16 hi/lo split, fp32 acc), CIN = 2*KW -> 64 oc.
// CTA = 128 pixels x 64 oc. Warp w -> pixels [P0+16w,+16); 8 n8 oc-tiles.
// 25 positions x 3 split-products x (KW/8) k-steps. B register-prefetched.
// SPLITOUT: epilogue re-splits bias+ReLU output to bf16 hi/lo pixel-major
// (feeds the next conv); else writes fp32 channel-major.
// ---------------------------------------------------------------------------
template <int KW, bool SPLITOUT>
__global__ void __launch_bounds__(256, (KW == 16) ? 2 : 1)
conv_hmma(const unsigned* __restrict__ ahi,   // [B][4624][KW]
          const unsigned* __restrict__ alo,
          const unsigned* __restrict__ wbf,   // [2][25][64][KW]
          const float* __restrict__ bias,     // [64]
          float* __restrict__ outf,           // [B][64][4624] (if !SPLITOUT)
          unsigned* __restrict__ ohi,         // [B][4624][32]  (if SPLITOUT)
          unsigned* __restrict__ olo)
{
    constexpr int QW    = KW / 4;             // uint4 per row
    constexpr int KSTEP = KW / 8;             // k16 steps
    constexpr int ASTR  = (KW == 16) ? 20 : 36;

    extern __shared__ float smem[];
    float*    sbias = smem;
    unsigned* sA    = (unsigned*)smem + 64;            // [2][AR2][ASTR]
    unsigned* sB    = sA + 2 * AR2 * ASTR;             // [2][64][ASTR]

    const int tid  = threadIdx.x;
    const int wid  = tid >> 5;
    const int lane = tid & 31;
    const int g    = lane >> 2;
    const int t    = lane & 3;

    const int b  = blockIdx.x / NPT2;
    const int tt = blockIdx.x - b * NPT2;
    const int P0 = 128 + 128 * tt;

    if (tid < 64) sbias[tid] = bias[tid];

    // ---- load A tile (both splits): rows P0-138 .. P0+265, zero-guarded ----
#pragma unroll 1
    for (int sp = 0; sp < 2; ++sp) {
        const uint4* src = (const uint4*)((sp ? alo : ahi) + (size_t)b * PIMG * KW);
        unsigned* dst = sA + sp * (AR2 * ASTR);
#pragma unroll 1
        for (int i = tid; i < AR2 * QW; i += 256) {
            const int r = i / QW, q4 = i - r * QW;
            const int p = P0 - 138 + r;
            uint4 v = make_uint4(0, 0, 0, 0);
            if (p >= 0 && p < PIMG) v = src[(size_t)p * QW + q4];
            *(uint4*)(dst + r * ASTR + 4 * q4) = v;
        }
    }

    float acc[8][4];
#pragma unroll
    for (int n8 = 0; n8 < 8; ++n8)
#pragma unroll
        for (int j = 0; j < 4; ++j) acc[n8][j] = 0.f;

    // ---- B prefetch regs covering [2][64][KW] ----
    constexpr int NBV = QW / 2;               // uint4 per thread
    const uint4* wq = (const uint4*)wbf;
    uint4 vr[NBV];
#pragma unroll
    for (int j = 0; j < NBV; ++j) {
        const int i = tid + j * 256;
        const int s = i / (64 * QW), rr = i - s * (64 * QW);
        vr[j] = wq[(size_t)(s * 25 + 0) * (64 * QW) + rr];
    }

    const int baserow = wid * 16;

#pragma unroll 1
    for (int pos = 0; pos < 25; ++pos) {
        __syncthreads();   // previous compute done reading sB
#pragma unroll
        for (int j = 0; j < NBV; ++j) {
            const int i = tid + j * 256;
            const int s = i / (64 * QW), rr = i - s * (64 * QW);
            const int row = rr / QW, q4 = rr - row * QW;
            *(uint4*)(sB + s * (64 * ASTR) + row * ASTR + 4 * q4) = vr[j];
        }
        __syncthreads();
        if (pos < 24) {
#pragma unroll
            for (int j = 0; j < NBV; ++j) {
                const int i = tid + j * 256;
                const int s = i / (64 * QW), rr = i - s * (64 * QW);
                vr[j] = wq[(size_t)(s * 25 + pos + 1) * (64 * QW) + rr];
            }
        }

        const int ky = pos / 5, kx = pos - 5 * ky;
        const int rowoff = 138 + (ky - 2) * PW + (kx - 2);
        const int arow = baserow + rowoff + g;

#pragma unroll
        for (int s = 0; s < 3; ++s) {
            // splits: 0: Ah*Bh, 1: Ah*Bl, 2: Al*Bh
            const unsigned* As = sA + ((s == 2) ? AR2 * ASTR : 0);
            const unsigned* Bs = sB + ((s == 1) ? 64 * ASTR : 0);
#pragma unroll
            for (int kk = 0; kk < KSTEP; ++kk) {
                const unsigned* ab = As + arow * ASTR + 8 * kk + t;
                const unsigned a0 = ab[0];
                const unsigned a1 = ab[8 * ASTR];
                const unsigned a2 = ab[4];
                const unsigned a3 = ab[8 * ASTR + 4];
#pragma unroll
                for (int n8 = 0; n8 < 8; ++n8) {
                    const unsigned* bb = Bs + (n8 * 8 + g) * ASTR + 8 * kk + t;
                    mma_bf16(acc[n8], a0, a1, a2, a3, bb[0], bb[4]);
                }
            }
        }
    }

    // ---- epilogue: bias + ReLU, interior pixels only ----
    const int p_lo = P0 + wid * 16 + g;
    const int p_hi = p_lo + 8;
    const int ylo = p_lo / PW, xlo = p_lo - ylo * PW;
    const int yhi = p_hi / PW, xhi = p_hi - yhi * PW;
    const bool v_lo = (ylo >= 2 && ylo < 66 && xlo >= 2 && xlo < 66);
    const bool v_hi = (yhi >= 2 && yhi < 66 && xhi >= 2 && xhi < 66);

    if constexpr (SPLITOUT) {
        unsigned* hb = ohi + (size_t)b * PIMG * 32;
        unsigned* lb = olo + (size_t)b * PIMG * 32;
#pragma unroll
        for (int n8 = 0; n8 < 8; ++n8) {
            const int oc = n8 * 8 + 2 * t;
            const float bv0 = sbias[oc], bv1 = sbias[oc + 1];
            const int widx = n8 * 4 + t;     // oc-pair word index
            if (v_lo) {
                const float u0 = fmaxf(acc[n8][0] + bv0, 0.f);
                const float u1 = fmaxf(acc[n8][1] + bv1, 0.f);
                hb[(size_t)p_lo * 32 + widx] = pack_split_hi(u0, u1);
                lb[(size_t)p_lo * 32 + widx] = pack_split_lo(u0, u1);
            }
            if (v_hi) {
                const float u0 = fmaxf(acc[n8][2] + bv0, 0.f);
                const float u1 = fmaxf(acc[n8][3] + bv1, 0.f);
                hb[(size_t)p_hi * 32 + widx] = pack_split_hi(u0, u1);
                lb[(size_t)p_hi * 32 + widx] = pack_split_lo(u0, u1);
            }
        }
    } else {
        float* ob = outf + (size_t)b * 64 * PIMG;
#pragma unroll
        for (int n8 = 0; n8 < 8; ++n8) {
            const int oc = n8 * 8 + 2 * t;
            const float bv0 = sbias[oc], bv1 = sbias[oc + 1];
            if (v_lo) {
                ob[(size_t)oc * PIMG + p_lo]       = fmaxf(acc[n8][0] + bv0, 0.f);
                ob[(size_t)(oc + 1) * PIMG + p_lo] = fmaxf(acc[n8][1] + bv1, 0.f);
            }
            if (v_hi) {
                ob[(size_t)oc * PIMG + p_hi]       = fmaxf(acc[n8][2] + bv0, 0.f);
                ob[(size_t)(oc + 1) * PIMG + p_hi] = fmaxf(acc[n8][3] + bv1, 0.f);
            }
        }
    }
}

// ---------------------------------------------------------------------------
// Final 5x5 conv, 64 -> 1, writes d_out (B,64,64). (Note: conv2's ReLU is
// NOT applied to conv3 input -- reference has no ReLU on conv2? It does:
// relu(conv1), relu(conv... reference: h=relu(conv0); h=relu(conv1); h=conv2.
// conv2 epilogue above applies ReLU only when !SPLITOUT -> that's layer 2
// (w1) whose output IS relu'd in the reference. Correct.)
// ---------------------------------------------------------------------------
__global__ void __launch_bounds__(256, 4)
conv3k(const float* __restrict__ in,
       const float* __restrict__ w2,
       const float* __restrict__ b2,
       float* __restrict__ out)
{
    extern __shared__ float smem[];
    float* tile = smem;
    float* ws   = smem + CHUNK3 * 8 * PW;

    const int blk   = blockIdx.x;
    const int ytile = blk & 15;
    const int b     = blk >> 4;
    const int y0    = ytile * 4;

    for (int i = threadIdx.x; i < 1600; i += 256) ws[i] = w2[i];

    const int yr = threadIdx.x >> 6;
    const int x  = threadIdx.x & 63;
    float acc = b2[0];

#pragma unroll 1
    for (int chunk = 0; chunk < 64 / CHUNK3; ++chunk) {
        __syncthreads();
        const float* src = in + ((size_t)b * 64 + chunk * CHUNK3) * PIMG
                              + (size_t)y0 * PW;
        for (int i = threadIdx.x; i < CHUNK3 * 8 * PW; i += 256) {
            const int ch = i / (8 * PW);
            const int r  = i - ch * (8 * PW);
            tile[i] = src[(size_t)ch * PIMG + r];
        }
        __syncthreads();

#pragma unroll 1
        for (int cl = 0; cl < CHUNK3; ++cl) {
            const float* t  = tile + cl * (8 * PW) + yr * PW + x;
            const float* wc = ws + (chunk * CHUNK3 + cl) * 25;
#pragma unroll
            for (int ky = 0; ky < 5; ++ky)
#pragma unroll
                for (int kx = 0; kx < 5; ++kx)
                    acc += wc[ky * 5 + kx] * t[ky * PW + kx];
        }
    }
    out[(size_t)b * 4096 + (size_t)(y0 + yr) * 64 + x] = acc;
}

// ---------------------------------------------------------------------------
// kernel_launch (graph-capturable)
// ---------------------------------------------------------------------------
extern "C" void kernel_launch(void* const* d_in, const int* in_sizes, int n_in,
                              void* d_out, int out_size)
{
    (void)in_sizes; (void)n_in; (void)out_size;

    const float* x  = (const float*)d_in[0];
    const float* w0 = (const float*)d_in[1];
    const float* b0 = (const float*)d_in[2];
    const float* w1 = (const float*)d_in[3];
    const float* b1 = (const float*)d_in[4];
    const float* w2 = (const float*)d_in[5];
    const float* b2 = (const float*)d_in[6];
    float* out = (float*)d_out;

    void *py2, *pahi0, *palo0, *pahi, *palo, *pwbf0, *pwbf1;
    cudaGetSymbolAddress(&py2,   g_y2);
    cudaGetSymbolAddress(&pahi0, g_ahi0);
    cudaGetSymbolAddress(&palo0, g_alo0);
    cudaGetSymbolAddress(&pahi,  g_ahi);
    cudaGetSymbolAddress(&palo,  g_alo);
    cudaGetSymbolAddress(&pwbf0, g_wbf0);
    cudaGetSymbolAddress(&pwbf1, g_wbf1);

    constexpr int SMEM_C1 = (64 + 2 * AR2 * 20 + 2 * 64 * 20) * 4;  //  75,136 B
    constexpr int SMEM_C2 = (64 + 2 * AR2 * 36 + 2 * 64 * 36) * 4;  // 135,040 B
    constexpr int SMEM3   = (CHUNK3 * 8 * PW + 1600) * 4;           //  41,216 B

    cudaFuncSetAttribute((const void*)conv_hmma<16, true>,
                         cudaFuncAttributeMaxDynamicSharedMemorySize, SMEM_C1);
    cudaFuncSetAttribute((const void*)conv_hmma<32, false>,
                         cudaFuncAttributeMaxDynamicSharedMemorySize, SMEM_C2);
    cudaFuncSetAttribute((const void*)conv3k,
                         cudaFuncAttributeMaxDynamicSharedMemorySize, SMEM3);

    rotate_kernel<<<BB * PW, 256>>>(x, (unsigned*)pahi0, (unsigned*)palo0);
    zb_a<<<BB, 256>>>((unsigned*)pahi, (unsigned*)palo);
    zb_y2<<<BB * 64, 256>>>((float*)py2);
    wprep_kernel<32><<<25, 256>>>(w0, (unsigned*)pwbf0);
    wprep_kernel<64><<<25, 256>>>(w1, (unsigned*)pwbf1);

    conv_hmma<16, true><<<BB * NPT2, 256, SMEM_C1>>>(
        (const unsigned*)pahi0, (const unsigned*)palo0,
        (const unsigned*)pwbf0, b0,
        nullptr, (unsigned*)pahi, (unsigned*)palo);

    conv_hmma<32, false><<<BB * NPT2, 256, SMEM_C2>>>(
        (const unsigned*)pahi, (const unsigned*)palo,
        (const unsigned*)pwbf1, b1,
        (float*)py2, nullptr, nullptr);

    conv3k<<<BB * 16, 256, SMEM3>>>((const float*)py2, w2, b2, out);
}